// round 1
// baseline (speedup 1.0000x reference)
#include <cuda_runtime.h>

#define BB 2
#define SS 1024
#define DMOD 1024
#define HH 16
#define DH 64
#define NR 21   // 2*MAX_REL+1

// ---- scratch (static device globals: no allocations allowed) ----
__device__ float g_Q[BB * SS * DMOD];
__device__ float g_K[BB * SS * DMOD];
__device__ float g_V[BB * SS * DMOD];
__device__ float g_X[BB * SS * DMOD];

// ============================================================================
// SGEMM: C[m,n] = sum_k A[m,k] * B[n,k] + bias[n]
// (both operands K-major row-major; this is exactly x @ W^T + b)
// 128x128 tile, BK=8, 256 threads, 8x8 per-thread microtile.
// ============================================================================
__global__ __launch_bounds__(256) void sgemm_abt(
    const float* __restrict__ A, const float* __restrict__ B,
    const float* __restrict__ bias, float* __restrict__ C,
    int M, int N, int K) {
    __shared__ float As[8 * 132];
    __shared__ float Bs[8 * 132];

    const int t = threadIdx.x;
    const int tx = t & 15;         // n-dir
    const int ty = t >> 4;         // m-dir
    const int m0 = blockIdx.y * 128;
    const int n0 = blockIdx.x * 128;

    float acc[8][8];
#pragma unroll
    for (int i = 0; i < 8; ++i)
#pragma unroll
        for (int j = 0; j < 8; ++j) acc[i][j] = 0.f;

    const int lr = t >> 1;            // 0..127
    const int lc = (t & 1) << 2;      // 0 or 4
    const float* Ap = A + (size_t)(m0 + lr) * K + lc;
    const float* Bp = B + (size_t)(n0 + lr) * K + lc;

    for (int k0 = 0; k0 < K; k0 += 8) {
        float4 av = *(const float4*)(Ap + k0);
        float4 bv = *(const float4*)(Bp + k0);
        __syncthreads();
        As[(lc + 0) * 132 + lr] = av.x;
        As[(lc + 1) * 132 + lr] = av.y;
        As[(lc + 2) * 132 + lr] = av.z;
        As[(lc + 3) * 132 + lr] = av.w;
        Bs[(lc + 0) * 132 + lr] = bv.x;
        Bs[(lc + 1) * 132 + lr] = bv.y;
        Bs[(lc + 2) * 132 + lr] = bv.z;
        Bs[(lc + 3) * 132 + lr] = bv.w;
        __syncthreads();
#pragma unroll
        for (int kk = 0; kk < 8; ++kk) {
            float4 a0 = *(const float4*)&As[kk * 132 + ty * 8];
            float4 a1 = *(const float4*)&As[kk * 132 + ty * 8 + 4];
            float4 b0 = *(const float4*)&Bs[kk * 132 + tx * 8];
            float4 b1 = *(const float4*)&Bs[kk * 132 + tx * 8 + 4];
            float a[8] = {a0.x, a0.y, a0.z, a0.w, a1.x, a1.y, a1.z, a1.w};
            float b[8] = {b0.x, b0.y, b0.z, b0.w, b1.x, b1.y, b1.z, b1.w};
#pragma unroll
            for (int i = 0; i < 8; ++i)
#pragma unroll
                for (int j = 0; j < 8; ++j) acc[i][j] += a[i] * b[j];
        }
    }

    float4 bi0 = *(const float4*)&bias[n0 + tx * 8];
    float4 bi1 = *(const float4*)&bias[n0 + tx * 8 + 4];
#pragma unroll
    for (int i = 0; i < 8; ++i) {
        const size_t row = (size_t)(m0 + ty * 8 + i) * N + n0 + tx * 8;
        float4 c0 = make_float4(acc[i][0] + bi0.x, acc[i][1] + bi0.y,
                                acc[i][2] + bi0.z, acc[i][3] + bi0.w);
        float4 c1 = make_float4(acc[i][4] + bi1.x, acc[i][5] + bi1.y,
                                acc[i][6] + bi1.z, acc[i][7] + bi1.w);
        *(float4*)&C[row] = c0;
        *(float4*)&C[row + 4] = c1;
    }
}

// ============================================================================
// Fused attention (no softmax; mask is a no-op in the reference).
// One block = one (b, h, 64-row q-tile). Streams k-tiles of 64.
//  - scores S = Q K^T + pp[q][class(k-q)], scaled by 1/32
//  - O += S @ V
//  - classSum[q][j] += S[q][k] over the clip-class of (k-q)
//  - epilogue: O += classSum @ rel_v_table
// ============================================================================
__global__ __launch_bounds__(256) void attn_kernel(
    const float* __restrict__ Qg, const float* __restrict__ Kg,
    const float* __restrict__ Vg, const float* __restrict__ rkt,
    const float* __restrict__ rvt, float* __restrict__ X) {
    extern __shared__ float sm[];
    float* Qt  = sm;                  // [64 d][68] q-contig (transposed)
    float* Kt  = Qt  + 64 * 68;       // [64 d][68] k-contig
    float* Vs  = Kt  + 64 * 68;       // [64 k][68] d-contig
    float* Ssm = Vs  + 64 * 68;       // [64 q][68] k-contig
    float* rk  = Ssm + 64 * 68;       // [21][64]
    float* rv  = rk  + NR * 64;       // [21][64]
    float* pp  = rv  + NR * 64;       // [64 q][21]
    float* cs  = pp  + 64 * NR;       // [64 q][21]

    const int t = threadIdx.x;
    const int tx = t & 15;     // 4-wide in k (scores) / d (output)
    const int ty = t >> 4;     // 4-wide in q
    const int q0 = blockIdx.x * 64;
    const int h  = blockIdx.y;
    const int b  = blockIdx.z;

    const float* Qb = Qg + ((size_t)b * SS + q0) * DMOD + h * DH;
    const float* Kb = Kg + (size_t)b * SS * DMOD + h * DH;
    const float* Vb = Vg + (size_t)b * SS * DMOD + h * DH;

    // load Q tile transposed
#pragma unroll
    for (int rep = 0; rep < 4; ++rep) {
        int lin = t + rep * 256;
        int r = lin >> 4;
        int d4 = (lin & 15) << 2;
        float4 v = *(const float4*)(Qb + (size_t)r * DMOD + d4);
        Qt[(d4 + 0) * 68 + r] = v.x;
        Qt[(d4 + 1) * 68 + r] = v.y;
        Qt[(d4 + 2) * 68 + r] = v.z;
        Qt[(d4 + 3) * 68 + r] = v.w;
    }
    for (int i = t; i < NR * 64; i += 256) { rk[i] = rkt[i]; rv[i] = rvt[i]; }
    __syncthreads();

    // pp[q][j] = Q[q] . rel_k_table[j];  zero classSum
    for (int e = t; e < 64 * NR; e += 256) {
        int q = e / NR, j = e - q * NR;
        float s = 0.f;
#pragma unroll 16
        for (int d = 0; d < 64; ++d) s += Qt[d * 68 + q] * rk[j * 64 + d];
        pp[e] = s;
        cs[e] = 0.f;
    }
    __syncthreads();

    float o[4][4];
#pragma unroll
    for (int i = 0; i < 4; ++i)
#pragma unroll
        for (int j = 0; j < 4; ++j) o[i][j] = 0.f;

    for (int kt = 0; kt < SS / 64; ++kt) {
        const int k0 = kt * 64;
        __syncthreads();   // previous tile fully consumed
#pragma unroll
        for (int rep = 0; rep < 4; ++rep) {
            int lin = t + rep * 256;
            int r = lin >> 4;
            int d4 = (lin & 15) << 2;
            float4 kv = *(const float4*)(Kb + (size_t)(k0 + r) * DMOD + d4);
            Kt[(d4 + 0) * 68 + r] = kv.x;
            Kt[(d4 + 1) * 68 + r] = kv.y;
            Kt[(d4 + 2) * 68 + r] = kv.z;
            Kt[(d4 + 3) * 68 + r] = kv.w;
            float4 vv = *(const float4*)(Vb + (size_t)(k0 + r) * DMOD + d4);
            *(float4*)&Vs[r * 68 + d4] = vv;
        }
        __syncthreads();

        // S = Q K^T (4x4 per thread)
        float s[4][4];
#pragma unroll
        for (int i = 0; i < 4; ++i)
#pragma unroll
            for (int j = 0; j < 4; ++j) s[i][j] = 0.f;
#pragma unroll 8
        for (int d = 0; d < 64; ++d) {
            float4 a4 = *(const float4*)&Qt[d * 68 + ty * 4];
            float4 b4 = *(const float4*)&Kt[d * 68 + tx * 4];
            float a[4] = {a4.x, a4.y, a4.z, a4.w};
            float bq[4] = {b4.x, b4.y, b4.z, b4.w};
#pragma unroll
            for (int i = 0; i < 4; ++i)
#pragma unroll
                for (int j = 0; j < 4; ++j) s[i][j] += a[i] * bq[j];
        }
        // + relative-K term, scale, stash in smem
#pragma unroll
        for (int i = 0; i < 4; ++i) {
            const int q = ty * 4 + i;
            const int qg = q0 + q;
#pragma unroll
            for (int j = 0; j < 4; ++j) {
                const int kg = k0 + tx * 4 + j;
                const int dlt = kg - qg;
                const int cls = dlt < -10 ? 0 : (dlt > 10 ? 20 : dlt + 10);
                Ssm[q * 68 + tx * 4 + j] =
                    (s[i][j] + pp[q * NR + cls]) * (1.0f / 32.0f);
            }
        }
        __syncthreads();

        // O += S @ V
#pragma unroll 8
        for (int k = 0; k < 64; ++k) {
            float4 v4 = *(const float4*)&Vs[k * 68 + tx * 4];
            float vb[4] = {v4.x, v4.y, v4.z, v4.w};
#pragma unroll
            for (int i = 0; i < 4; ++i) {
                float sv = Ssm[(ty * 4 + i) * 68 + k];
#pragma unroll
                for (int j = 0; j < 4; ++j) o[i][j] += sv * vb[j];
            }
        }

        // classSum accumulation (4 threads per q row; middle classes unique->no race)
        {
            const int tq = t >> 2;
            const int sub = t & 3;
            const int qg = q0 + tq;
            const int kk0 = sub * 16;
            float l0 = 0.f, l20 = 0.f;
#pragma unroll
            for (int kk = 0; kk < 16; ++kk) {
                float v = Ssm[tq * 68 + kk0 + kk];
                int dlt = k0 + kk0 + kk - qg;
                if (dlt <= -10)      l0  += v;
                else if (dlt >= 10)  l20 += v;
                else                 cs[tq * NR + dlt + 10] += v;
            }
            atomicAdd(&cs[tq * NR + 0],  l0);
            atomicAdd(&cs[tq * NR + 20], l20);
        }
    }
    __syncthreads();

    // O += classSum @ rel_v_table
#pragma unroll
    for (int jj = 0; jj < NR; ++jj) {
        float4 r4 = *(const float4*)&rv[jj * 64 + tx * 4];
        float rb[4] = {r4.x, r4.y, r4.z, r4.w};
#pragma unroll
        for (int i = 0; i < 4; ++i) {
            float c = cs[(ty * 4 + i) * NR + jj];
#pragma unroll
            for (int j = 0; j < 4; ++j) o[i][j] += c * rb[j];
        }
    }

    // write back (transposed-back layout: X[b, q, h*64 + d])
    float* Xb = X + ((size_t)b * SS + q0) * DMOD + h * DH;
#pragma unroll
    for (int i = 0; i < 4; ++i) {
        *(float4*)&Xb[(size_t)(ty * 4 + i) * DMOD + tx * 4] =
            make_float4(o[i][0], o[i][1], o[i][2], o[i][3]);
    }
}

// ============================================================================
// launch
// ============================================================================
extern "C" void kernel_launch(void* const* d_in, const int* in_sizes, int n_in,
                              void* d_out, int out_size) {
    const float* q   = (const float*)d_in[0];
    const float* k   = (const float*)d_in[1];
    const float* v   = (const float*)d_in[2];
    // d_in[3] = mask (no-op in reference)
    const float* Wq  = (const float*)d_in[4];
    const float* bq  = (const float*)d_in[5];
    const float* Wk  = (const float*)d_in[6];
    const float* bk  = (const float*)d_in[7];
    const float* Wv  = (const float*)d_in[8];
    const float* bv  = (const float*)d_in[9];
    const float* W0  = (const float*)d_in[10];
    const float* b0  = (const float*)d_in[11];
    const float* rkt = (const float*)d_in[12];
    const float* rvt = (const float*)d_in[13];

    float *Qp, *Kp, *Vp, *Xp;
    cudaGetSymbolAddress((void**)&Qp, g_Q);
    cudaGetSymbolAddress((void**)&Kp, g_K);
    cudaGetSymbolAddress((void**)&Vp, g_V);
    cudaGetSymbolAddress((void**)&Xp, g_X);

    const int M = BB * SS;  // 2048
    dim3 gproj(DMOD / 128, M / 128);

    sgemm_abt<<<gproj, 256>>>(q, Wq, bq, Qp, M, DMOD, DMOD);
    sgemm_abt<<<gproj, 256>>>(k, Wk, bk, Kp, M, DMOD, DMOD);
    sgemm_abt<<<gproj, 256>>>(v, Wv, bv, Vp, M, DMOD, DMOD);

    const int SMEM = (4 * 64 * 68 + 4 * NR * 64 + 0) * 4 + 2 * 64 * NR * 4
                     - 2 * NR * 64 * 4;  // = 91136 bytes
    // (Qt,Kt,Vs,Ssm: 4*64*68 floats) + (rk,rv: 2*21*64) + (pp,cs: 2*64*21)
    static_assert((4 * 64 * 68 + 2 * NR * 64 + 2 * 64 * NR) * 4 == 91136, "smem");
    cudaFuncSetAttribute(attn_kernel,
                         cudaFuncAttributeMaxDynamicSharedMemorySize, 91136);
    attn_kernel<<<dim3(SS / 64, HH, BB), 256, 91136>>>(Qp, Kp, Vp, rkt, rvt, Xp);

    sgemm_abt<<<gproj, 256>>>(Xp, W0, b0, (float*)d_out, M, DMOD, DMOD);
}

// round 3
// speedup vs baseline: 1.3929x; 1.3929x over previous
#include <cuda_runtime.h>
#include <cuda_bf16.h>
#include <cstdint>

#define BB 2
#define SS 1024
#define DMOD 1024
#define HH 16
#define DH 64
#define NR 21     // 2*MAX_REL+1
#define K3 3072   // 3 * DMOD (split-concatenated K)

// ============================================================================
// scratch (static device globals: no allocations allowed)
// ============================================================================
__device__ float g_Q[BB * SS * DMOD];
__device__ float g_K[BB * SS * DMOD];
__device__ float g_V[BB * SS * DMOD];
__device__ float g_X[BB * SS * DMOD];

// split-concatenated bf16 operands, row-major [rows, K3]
__device__ __nv_bfloat16 g_q2[BB * SS * K3];
__device__ __nv_bfloat16 g_k2[BB * SS * K3];
__device__ __nv_bfloat16 g_v2[BB * SS * K3];
__device__ __nv_bfloat16 g_x2[BB * SS * K3];
__device__ __nv_bfloat16 g_wq2[DMOD * K3];
__device__ __nv_bfloat16 g_wk2[DMOD * K3];
__device__ __nv_bfloat16 g_wv2[DMOD * K3];
__device__ __nv_bfloat16 g_w02[DMOD * K3];

// ============================================================================
// split kernel: fp32 -> bf16 hi/lo, written K-concatenated.
//   act  (A-side): [0,K)=hi  [K,2K)=lo  [2K,3K)=hi
//   wt   (B-side): [0,K)=hi  [K,2K)=hi  [2K,3K)=lo
// so A'.B'^T over K3 = Ah.Bh + Al.Bh + Ah.Bl  (AlBl ~2^-16 dropped)
// ============================================================================
__global__ __launch_bounds__(256) void split_kernel(
    const float* __restrict__ in, __nv_bfloat16* __restrict__ out,
    int n, int is_act) {
    int i = blockIdx.x * blockDim.x + threadIdx.x;
    if (i >= n) return;
    int m = i >> 10;          // K = 1024
    int k = i & 1023;
    float x = in[i];
    __nv_bfloat16 h = __float2bfloat16_rn(x);
    float r = x - __bfloat162float(h);
    __nv_bfloat16 l = __float2bfloat16_rn(r);
    size_t base = (size_t)m * K3 + k;
    out[base] = h;
    if (is_act) {
        out[base + 1024] = l;
        out[base + 2048] = h;
    } else {
        out[base + 1024] = h;
        out[base + 2048] = l;
    }
}

// ============================================================================
// mma.sync helpers
// ============================================================================
__device__ __forceinline__ uint32_t smem_u32(const void* p) {
    uint32_t a;
    asm("{ .reg .u64 t; cvta.to.shared.u64 t, %1; cvt.u32.u64 %0, t; }"
        : "=r"(a) : "l"(p));
    return a;
}

__device__ __forceinline__ void ldmx4(uint32_t& r0, uint32_t& r1,
                                      uint32_t& r2, uint32_t& r3,
                                      uint32_t addr) {
    asm volatile(
        "ldmatrix.sync.aligned.m8n8.x4.shared.b16 {%0,%1,%2,%3}, [%4];"
        : "=r"(r0), "=r"(r1), "=r"(r2), "=r"(r3) : "r"(addr));
}

__device__ __forceinline__ void mma16816(float* c, const uint32_t* a,
                                         const uint32_t* b) {
    asm volatile(
        "mma.sync.aligned.m16n8k16.row.col.f32.bf16.bf16.f32 "
        "{%0,%1,%2,%3}, {%4,%5,%6,%7}, {%8,%9}, {%0,%1,%2,%3};"
        : "+f"(c[0]), "+f"(c[1]), "+f"(c[2]), "+f"(c[3])
        : "r"(a[0]), "r"(a[1]), "r"(a[2]), "r"(a[3]), "r"(b[0]), "r"(b[1]));
}

// ============================================================================
// bf16 HMMA GEMM over K3:  C[m,n] = sum_k A'[m,k]*B'[n,k] + bias[n]
// 128x128 tile, BK=32, 256 thr (8 warps = 2Mx4N), double-buffered smem.
// ============================================================================
struct GemmArgs {
    const __nv_bfloat16* A[3];
    const __nv_bfloat16* B[3];
    const float* bias[3];
    float* C[3];
};

#define BK 32
#define RS 40                 // smem row stride in halves (80B, ldmatrix conflict-free)
#define BUFH (128 * RS)       // halves per buffer

__global__ __launch_bounds__(256) void gemm_mma(GemmArgs ga, int N) {
    __shared__ __align__(16) __nv_bfloat16 As[2][BUFH];
    __shared__ __align__(16) __nv_bfloat16 Bs[2][BUFH];

    const int t = threadIdx.x;
    const int lane = t & 31;
    const int wid = t >> 5;
    const int wm = (wid & 1) * 64;       // warp m-offset in tile
    const int wn = (wid >> 1) * 32;      // warp n-offset in tile
    const int grp = lane >> 2;
    const int tig = lane & 3;
    const int z = blockIdx.z;
    const int m0 = blockIdx.y * 128;
    const int n0 = blockIdx.x * 128;

    const __nv_bfloat16* Ag = ga.A[z];
    const __nv_bfloat16* Bg = ga.B[z];
    const float* bias = ga.bias[z];
    float* C = ga.C[z];

    // global load mapping: thread t -> row t>>1, 32B chunk (t&1)
    const int lrow = t >> 1;
    const int lcol = (t & 1) * 16;       // halves
    const __nv_bfloat16* Ap = Ag + (size_t)(m0 + lrow) * K3 + lcol;
    const __nv_bfloat16* Bp = Bg + (size_t)(n0 + lrow) * K3 + lcol;
    // smem store byte offset for this thread (within a buffer)
    const uint32_t sst = lrow * (RS * 2) + lcol * 2;

    const uint32_t asb = smem_u32(As);
    const uint32_t bsb = smem_u32(Bs);

    // ldmatrix address components
    const uint32_t a_row = wm + (lane & 15);
    const uint32_t a_k   = (lane >> 4) * 8;
    const uint32_t a_base = asb + a_row * (RS * 2) + a_k * 2;
    const uint32_t b_row = wn + (lane & 7) + ((lane >> 4) & 1) * 8;
    const uint32_t b_k   = ((lane >> 3) & 1) * 8;
    const uint32_t b_base = bsb + b_row * (RS * 2) + b_k * 2;

    float acc[4][4][4];
#pragma unroll
    for (int mi = 0; mi < 4; ++mi)
#pragma unroll
        for (int ni = 0; ni < 4; ++ni)
#pragma unroll
            for (int r = 0; r < 4; ++r) acc[mi][ni][r] = 0.f;

    // preload tile 0
    uint4 pa0 = *(const uint4*)(Ap);
    uint4 pa1 = *(const uint4*)(Ap + 8);
    uint4 pb0 = *(const uint4*)(Bp);
    uint4 pb1 = *(const uint4*)(Bp + 8);
    *(uint4*)((char*)As + sst)      = pa0;
    *(uint4*)((char*)As + sst + 16) = pa1;
    *(uint4*)((char*)Bs + sst)      = pb0;
    *(uint4*)((char*)Bs + sst + 16) = pb1;
    __syncthreads();

    const int NT = K3 / BK;   // 96
    for (int kt = 0; kt < NT; ++kt) {
        const int buf = kt & 1;
        const bool has_next = (kt + 1 < NT);
        if (has_next) {
            const __nv_bfloat16* an = Ap + (size_t)(kt + 1) * BK;
            const __nv_bfloat16* bn = Bp + (size_t)(kt + 1) * BK;
            pa0 = *(const uint4*)(an);
            pa1 = *(const uint4*)(an + 8);
            pb0 = *(const uint4*)(bn);
            pb1 = *(const uint4*)(bn + 8);
        }

        const uint32_t abuf = a_base + buf * (BUFH * 2);
        const uint32_t bbuf = b_base + buf * (BUFH * 2);
#pragma unroll
        for (int ks = 0; ks < 2; ++ks) {
            uint32_t a[4][4], b[4][2];
#pragma unroll
            for (int mi = 0; mi < 4; ++mi)
                ldmx4(a[mi][0], a[mi][1], a[mi][2], a[mi][3],
                      abuf + mi * 16 * (RS * 2) + ks * 32);
#pragma unroll
            for (int nb = 0; nb < 2; ++nb)
                ldmx4(b[nb * 2][0], b[nb * 2][1], b[nb * 2 + 1][0],
                      b[nb * 2 + 1][1],
                      bbuf + nb * 16 * (RS * 2) + ks * 32);
#pragma unroll
            for (int mi = 0; mi < 4; ++mi)
#pragma unroll
                for (int ni = 0; ni < 4; ++ni)
                    mma16816(acc[mi][ni], a[mi], b[ni]);
        }

        if (has_next) {
            const uint32_t nb = (buf ^ 1);
            *(uint4*)((char*)As + nb * (BUFH * 2) + sst)      = pa0;
            *(uint4*)((char*)As + nb * (BUFH * 2) + sst + 16) = pa1;
            *(uint4*)((char*)Bs + nb * (BUFH * 2) + sst)      = pb0;
            *(uint4*)((char*)Bs + nb * (BUFH * 2) + sst + 16) = pb1;
        }
        __syncthreads();
    }

    // epilogue: fragment -> global, + bias
#pragma unroll
    for (int ni = 0; ni < 4; ++ni) {
        const int col = n0 + wn + ni * 8 + tig * 2;
        const float2 bv = *(const float2*)&bias[col];
#pragma unroll
        for (int mi = 0; mi < 4; ++mi) {
            const int row = m0 + wm + mi * 16 + grp;
            float2 v0 = make_float2(acc[mi][ni][0] + bv.x, acc[mi][ni][1] + bv.y);
            float2 v1 = make_float2(acc[mi][ni][2] + bv.x, acc[mi][ni][3] + bv.y);
            *(float2*)&C[(size_t)row * N + col]       = v0;
            *(float2*)&C[(size_t)(row + 8) * N + col] = v1;
        }
    }
}

// ============================================================================
// Fused attention (fp32, unchanged from round 1; no softmax, mask no-op)
// ============================================================================
__global__ __launch_bounds__(256) void attn_kernel(
    const float* __restrict__ Qg, const float* __restrict__ Kg,
    const float* __restrict__ Vg, const float* __restrict__ rkt,
    const float* __restrict__ rvt, float* __restrict__ X) {
    extern __shared__ float sm[];
    float* Qt  = sm;
    float* Kt  = Qt  + 64 * 68;
    float* Vs  = Kt  + 64 * 68;
    float* Ssm = Vs  + 64 * 68;
    float* rk  = Ssm + 64 * 68;
    float* rv  = rk  + NR * 64;
    float* pp  = rv  + NR * 64;
    float* cs  = pp  + 64 * NR;

    const int t = threadIdx.x;
    const int tx = t & 15;
    const int ty = t >> 4;
    const int q0 = blockIdx.x * 64;
    const int h  = blockIdx.y;
    const int b  = blockIdx.z;

    const float* Qb = Qg + ((size_t)b * SS + q0) * DMOD + h * DH;
    const float* Kb = Kg + (size_t)b * SS * DMOD + h * DH;
    const float* Vb = Vg + (size_t)b * SS * DMOD + h * DH;

#pragma unroll
    for (int rep = 0; rep < 4; ++rep) {
        int lin = t + rep * 256;
        int r = lin >> 4;
        int d4 = (lin & 15) << 2;
        float4 v = *(const float4*)(Qb + (size_t)r * DMOD + d4);
        Qt[(d4 + 0) * 68 + r] = v.x;
        Qt[(d4 + 1) * 68 + r] = v.y;
        Qt[(d4 + 2) * 68 + r] = v.z;
        Qt[(d4 + 3) * 68 + r] = v.w;
    }
    for (int i = t; i < NR * 64; i += 256) { rk[i] = rkt[i]; rv[i] = rvt[i]; }
    __syncthreads();

    for (int e = t; e < 64 * NR; e += 256) {
        int q = e / NR, j = e - q * NR;
        float s = 0.f;
#pragma unroll 16
        for (int d = 0; d < 64; ++d) s += Qt[d * 68 + q] * rk[j * 64 + d];
        pp[e] = s;
        cs[e] = 0.f;
    }
    __syncthreads();

    float o[4][4];
#pragma unroll
    for (int i = 0; i < 4; ++i)
#pragma unroll
        for (int j = 0; j < 4; ++j) o[i][j] = 0.f;

    for (int kt = 0; kt < SS / 64; ++kt) {
        const int k0 = kt * 64;
        __syncthreads();
#pragma unroll
        for (int rep = 0; rep < 4; ++rep) {
            int lin = t + rep * 256;
            int r = lin >> 4;
            int d4 = (lin & 15) << 2;
            float4 kv = *(const float4*)(Kb + (size_t)(k0 + r) * DMOD + d4);
            Kt[(d4 + 0) * 68 + r] = kv.x;
            Kt[(d4 + 1) * 68 + r] = kv.y;
            Kt[(d4 + 2) * 68 + r] = kv.z;
            Kt[(d4 + 3) * 68 + r] = kv.w;
            float4 vv = *(const float4*)(Vb + (size_t)(k0 + r) * DMOD + d4);
            *(float4*)&Vs[r * 68 + d4] = vv;
        }
        __syncthreads();

        float s[4][4];
#pragma unroll
        for (int i = 0; i < 4; ++i)
#pragma unroll
            for (int j = 0; j < 4; ++j) s[i][j] = 0.f;
#pragma unroll 8
        for (int d = 0; d < 64; ++d) {
            float4 a4 = *(const float4*)&Qt[d * 68 + ty * 4];
            float4 b4 = *(const float4*)&Kt[d * 68 + tx * 4];
            float a[4] = {a4.x, a4.y, a4.z, a4.w};
            float bq[4] = {b4.x, b4.y, b4.z, b4.w};
#pragma unroll
            for (int i = 0; i < 4; ++i)
#pragma unroll
                for (int j = 0; j < 4; ++j) s[i][j] += a[i] * bq[j];
        }
#pragma unroll
        for (int i = 0; i < 4; ++i) {
            const int q = ty * 4 + i;
            const int qg = q0 + q;
#pragma unroll
            for (int j = 0; j < 4; ++j) {
                const int kg = k0 + tx * 4 + j;
                const int dlt = kg - qg;
                const int cls = dlt < -10 ? 0 : (dlt > 10 ? 20 : dlt + 10);
                Ssm[q * 68 + tx * 4 + j] =
                    (s[i][j] + pp[q * NR + cls]) * (1.0f / 32.0f);
            }
        }
        __syncthreads();

#pragma unroll 8
        for (int k = 0; k < 64; ++k) {
            float4 v4 = *(const float4*)&Vs[k * 68 + tx * 4];
            float vb[4] = {v4.x, v4.y, v4.z, v4.w};
#pragma unroll
            for (int i = 0; i < 4; ++i) {
                float sv = Ssm[(ty * 4 + i) * 68 + k];
#pragma unroll
                for (int j = 0; j < 4; ++j) o[i][j] += sv * vb[j];
            }
        }

        {
            const int tq = t >> 2;
            const int sub = t & 3;
            const int qg = q0 + tq;
            const int kk0 = sub * 16;
            float l0 = 0.f, l20 = 0.f;
#pragma unroll
            for (int kk = 0; kk < 16; ++kk) {
                float v = Ssm[tq * 68 + kk0 + kk];
                int dlt = k0 + kk0 + kk - qg;
                if (dlt <= -10)      l0  += v;
                else if (dlt >= 10)  l20 += v;
                else                 cs[tq * NR + dlt + 10] += v;
            }
            atomicAdd(&cs[tq * NR + 0],  l0);
            atomicAdd(&cs[tq * NR + 20], l20);
        }
    }
    __syncthreads();

#pragma unroll
    for (int jj = 0; jj < NR; ++jj) {
        float4 r4 = *(const float4*)&rv[jj * 64 + tx * 4];
        float rb[4] = {r4.x, r4.y, r4.z, r4.w};
#pragma unroll
        for (int i = 0; i < 4; ++i) {
            float c = cs[(ty * 4 + i) * NR + jj];
#pragma unroll
            for (int j = 0; j < 4; ++j) o[i][j] += c * rb[j];
        }
    }

    float* Xb = X + ((size_t)b * SS + q0) * DMOD + h * DH;
#pragma unroll
    for (int i = 0; i < 4; ++i) {
        *(float4*)&Xb[(size_t)(ty * 4 + i) * DMOD + tx * 4] =
            make_float4(o[i][0], o[i][1], o[i][2], o[i][3]);
    }
}

// ============================================================================
// launch
// ============================================================================
extern "C" void kernel_launch(void* const* d_in, const int* in_sizes, int n_in,
                              void* d_out, int out_size) {
    const float* q   = (const float*)d_in[0];
    const float* k   = (const float*)d_in[1];
    const float* v   = (const float*)d_in[2];
    const float* Wq  = (const float*)d_in[4];
    const float* bq  = (const float*)d_in[5];
    const float* Wk  = (const float*)d_in[6];
    const float* bk  = (const float*)d_in[7];
    const float* Wv  = (const float*)d_in[8];
    const float* bv  = (const float*)d_in[9];
    const float* W0  = (const float*)d_in[10];
    const float* b0  = (const float*)d_in[11];
    const float* rkt = (const float*)d_in[12];
    const float* rvt = (const float*)d_in[13];

    float *Qp, *Kp, *Vp, *Xp;
    cudaGetSymbolAddress((void**)&Qp, g_Q);
    cudaGetSymbolAddress((void**)&Kp, g_K);
    cudaGetSymbolAddress((void**)&Vp, g_V);
    cudaGetSymbolAddress((void**)&Xp, g_X);
    __nv_bfloat16 *q2, *k2, *v2, *x2, *wq2, *wk2, *wv2, *w02;
    cudaGetSymbolAddress((void**)&q2, g_q2);
    cudaGetSymbolAddress((void**)&k2, g_k2);
    cudaGetSymbolAddress((void**)&v2, g_v2);
    cudaGetSymbolAddress((void**)&x2, g_x2);
    cudaGetSymbolAddress((void**)&wq2, g_wq2);
    cudaGetSymbolAddress((void**)&wk2, g_wk2);
    cudaGetSymbolAddress((void**)&wv2, g_wv2);
    cudaGetSymbolAddress((void**)&w02, g_w02);

    const int M = BB * SS;          // 2048
    const int NACT = M * DMOD;      // 2M elements
    const int NW = DMOD * DMOD;     // 1M elements

    // splits (act layout for A-side operands, wt layout for B-side)
    split_kernel<<<(NACT + 255) / 256, 256>>>(q, q2, NACT, 1);
    split_kernel<<<(NACT + 255) / 256, 256>>>(k, k2, NACT, 1);
    split_kernel<<<(NACT + 255) / 256, 256>>>(v, v2, NACT, 1);
    split_kernel<<<(NW + 255) / 256, 256>>>(Wq, wq2, NW, 0);
    split_kernel<<<(NW + 255) / 256, 256>>>(Wk, wk2, NW, 0);
    split_kernel<<<(NW + 255) / 256, 256>>>(Wv, wv2, NW, 0);
    split_kernel<<<(NW + 255) / 256, 256>>>(W0, w02, NW, 0);

    // fused q/k/v projections: grid z selects which GEMM
    GemmArgs pa;
    pa.A[0] = q2;  pa.A[1] = k2;  pa.A[2] = v2;
    pa.B[0] = wq2; pa.B[1] = wk2; pa.B[2] = wv2;
    pa.bias[0] = bq; pa.bias[1] = bk; pa.bias[2] = bv;
    pa.C[0] = Qp; pa.C[1] = Kp; pa.C[2] = Vp;
    gemm_mma<<<dim3(DMOD / 128, M / 128, 3), 256>>>(pa, DMOD);

    // fused attention (fp32)
    cudaFuncSetAttribute(attn_kernel,
                         cudaFuncAttributeMaxDynamicSharedMemorySize, 91136);
    attn_kernel<<<dim3(SS / 64, HH, BB), 256, 91136>>>(Qp, Kp, Vp, rkt, rvt, Xp);

    // output projection
    split_kernel<<<(NACT + 255) / 256, 256>>>(Xp, x2, NACT, 1);
    GemmArgs oa;
    oa.A[0] = x2;  oa.A[1] = x2;  oa.A[2] = x2;
    oa.B[0] = w02; oa.B[1] = w02; oa.B[2] = w02;
    oa.bias[0] = b0; oa.bias[1] = b0; oa.bias[2] = b0;
    oa.C[0] = (float*)d_out; oa.C[1] = (float*)d_out; oa.C[2] = (float*)d_out;
    gemm_mma<<<dim3(DMOD / 128, M / 128, 1), 256>>>(oa, DMOD);
}

// round 5
// speedup vs baseline: 1.4705x; 1.0557x over previous
#include <cuda_runtime.h>
#include <cuda_bf16.h>
#include <cstdint>

#define BB 2
#define SS 1024
#define DMOD 1024
#define HH 16
#define DH 64
#define NR 21     // 2*MAX_REL+1
#define K3 3072   // 3 * DMOD (split-concatenated K)

// ============================================================================
// scratch (static device globals: no allocations allowed)
// ============================================================================
__device__ float g_Q[BB * SS * DMOD];
__device__ float g_K[BB * SS * DMOD];
__device__ float g_V[BB * SS * DMOD];
__device__ float g_X[BB * SS * DMOD];

// split-concatenated bf16 operands, row-major [rows, K3]
__device__ __nv_bfloat16 g_q2[BB * SS * K3];
__device__ __nv_bfloat16 g_k2[BB * SS * K3];
__device__ __nv_bfloat16 g_v2[BB * SS * K3];
__device__ __nv_bfloat16 g_x2[BB * SS * K3];
__device__ __nv_bfloat16 g_wq2[DMOD * K3];
__device__ __nv_bfloat16 g_wk2[DMOD * K3];
__device__ __nv_bfloat16 g_wv2[DMOD * K3];
__device__ __nv_bfloat16 g_w02[DMOD * K3];

// ============================================================================
// batched split kernel: fp32 -> bf16 hi/lo, written K-concatenated.
//   act  (A-side): [0,K)=hi  [K,2K)=lo  [2K,3K)=hi
//   wt   (B-side): [0,K)=hi  [K,2K)=hi  [2K,3K)=lo
// so A'.B'^T over K3 = Ah.Bh + Al.Bh + Ah.Bl  (AlBl ~2^-16 dropped)
// ============================================================================
struct SplitPack {
    const float* in[4];
    __nv_bfloat16* out[4];
};

__global__ __launch_bounds__(256) void split_multi(SplitPack p, int n, int is_act) {
    int i = blockIdx.x * blockDim.x + threadIdx.x;
    if (i >= n) return;
    const float* in = p.in[blockIdx.y];
    __nv_bfloat16* out = p.out[blockIdx.y];
    int m = i >> 10;          // K = 1024
    int k = i & 1023;
    float x = in[i];
    __nv_bfloat16 h = __float2bfloat16_rn(x);
    float r = x - __bfloat162float(h);
    __nv_bfloat16 l = __float2bfloat16_rn(r);
    size_t base = (size_t)m * K3 + k;
    out[base] = h;
    if (is_act) {
        out[base + 1024] = l;
        out[base + 2048] = h;
    } else {
        out[base + 1024] = h;
        out[base + 2048] = l;
    }
}

// ============================================================================
// mma.sync helpers
// ============================================================================
__device__ __forceinline__ uint32_t smem_u32(const void* p) {
    uint32_t a;
    asm("{ .reg .u64 t; cvta.to.shared.u64 t, %1; cvt.u32.u64 %0, t; }"
        : "=r"(a) : "l"(p));
    return a;
}

__device__ __forceinline__ void ldmx4(uint32_t& r0, uint32_t& r1,
                                      uint32_t& r2, uint32_t& r3,
                                      uint32_t addr) {
    asm volatile(
        "ldmatrix.sync.aligned.m8n8.x4.shared.b16 {%0,%1,%2,%3}, [%4];"
        : "=r"(r0), "=r"(r1), "=r"(r2), "=r"(r3) : "r"(addr));
}

__device__ __forceinline__ void ldmx4t(uint32_t& r0, uint32_t& r1,
                                       uint32_t& r2, uint32_t& r3,
                                       uint32_t addr) {
    asm volatile(
        "ldmatrix.sync.aligned.m8n8.x4.trans.shared.b16 {%0,%1,%2,%3}, [%4];"
        : "=r"(r0), "=r"(r1), "=r"(r2), "=r"(r3) : "r"(addr));
}

__device__ __forceinline__ void mma16816(float* c, const uint32_t* a,
                                         const uint32_t* b) {
    asm volatile(
        "mma.sync.aligned.m16n8k16.row.col.f32.bf16.bf16.f32 "
        "{%0,%1,%2,%3}, {%4,%5,%6,%7}, {%8,%9}, {%0,%1,%2,%3};"
        : "+f"(c[0]), "+f"(c[1]), "+f"(c[2]), "+f"(c[3])
        : "r"(a[0]), "r"(a[1]), "r"(a[2]), "r"(a[3]), "r"(b[0]), "r"(b[1]));
}

// split-store 4 consecutive floats to hi/lo bf16 planes
__device__ __forceinline__ void split_store4(float4 v, __nv_bfloat16* Hp,
                                             __nv_bfloat16* Lp, int idx) {
    __nv_bfloat16 h0 = __float2bfloat16_rn(v.x);
    __nv_bfloat16 h1 = __float2bfloat16_rn(v.y);
    __nv_bfloat16 h2 = __float2bfloat16_rn(v.z);
    __nv_bfloat16 h3 = __float2bfloat16_rn(v.w);
    __nv_bfloat16 l0 = __float2bfloat16_rn(v.x - __bfloat162float(h0));
    __nv_bfloat16 l1 = __float2bfloat16_rn(v.y - __bfloat162float(h1));
    __nv_bfloat16 l2 = __float2bfloat16_rn(v.z - __bfloat162float(h2));
    __nv_bfloat16 l3 = __float2bfloat16_rn(v.w - __bfloat162float(h3));
    *(__nv_bfloat162*)(Hp + idx)     = __halves2bfloat162(h0, h1);
    *(__nv_bfloat162*)(Hp + idx + 2) = __halves2bfloat162(h2, h3);
    *(__nv_bfloat162*)(Lp + idx)     = __halves2bfloat162(l0, l1);
    *(__nv_bfloat162*)(Lp + idx + 2) = __halves2bfloat162(l2, l3);
}

// ============================================================================
// bf16 HMMA GEMM over K3 (verified in round 3)
// ============================================================================
struct GemmArgs {
    const __nv_bfloat16* A[3];
    const __nv_bfloat16* B[3];
    const float* bias[3];
    float* C[3];
};

#define BK 32
#define RS 40
#define BUFH (128 * RS)

__global__ __launch_bounds__(256) void gemm_mma(GemmArgs ga, int N) {
    __shared__ __align__(16) __nv_bfloat16 As[2][BUFH];
    __shared__ __align__(16) __nv_bfloat16 Bs[2][BUFH];

    const int t = threadIdx.x;
    const int lane = t & 31;
    const int wid = t >> 5;
    const int wm = (wid & 1) * 64;
    const int wn = (wid >> 1) * 32;
    const int grp = lane >> 2;
    const int tig = lane & 3;
    const int z = blockIdx.z;
    const int m0 = blockIdx.y * 128;
    const int n0 = blockIdx.x * 128;

    const __nv_bfloat16* Ag = ga.A[z];
    const __nv_bfloat16* Bg = ga.B[z];
    const float* bias = ga.bias[z];
    float* C = ga.C[z];

    const int lrow = t >> 1;
    const int lcol = (t & 1) * 16;
    const __nv_bfloat16* Ap = Ag + (size_t)(m0 + lrow) * K3 + lcol;
    const __nv_bfloat16* Bp = Bg + (size_t)(n0 + lrow) * K3 + lcol;
    const uint32_t sst = lrow * (RS * 2) + lcol * 2;

    const uint32_t asb = smem_u32(As);
    const uint32_t bsb = smem_u32(Bs);

    const uint32_t a_row = wm + (lane & 15);
    const uint32_t a_k   = (lane >> 4) * 8;
    const uint32_t a_base = asb + a_row * (RS * 2) + a_k * 2;
    const uint32_t b_row = wn + (lane & 7) + ((lane >> 4) & 1) * 8;
    const uint32_t b_k   = ((lane >> 3) & 1) * 8;
    const uint32_t b_base = bsb + b_row * (RS * 2) + b_k * 2;

    float acc[4][4][4];
#pragma unroll
    for (int mi = 0; mi < 4; ++mi)
#pragma unroll
        for (int ni = 0; ni < 4; ++ni)
#pragma unroll
            for (int r = 0; r < 4; ++r) acc[mi][ni][r] = 0.f;

    uint4 pa0 = *(const uint4*)(Ap);
    uint4 pa1 = *(const uint4*)(Ap + 8);
    uint4 pb0 = *(const uint4*)(Bp);
    uint4 pb1 = *(const uint4*)(Bp + 8);
    *(uint4*)((char*)As + sst)      = pa0;
    *(uint4*)((char*)As + sst + 16) = pa1;
    *(uint4*)((char*)Bs + sst)      = pb0;
    *(uint4*)((char*)Bs + sst + 16) = pb1;
    __syncthreads();

    const int NT = K3 / BK;
    for (int kt = 0; kt < NT; ++kt) {
        const int buf = kt & 1;
        const bool has_next = (kt + 1 < NT);
        if (has_next) {
            const __nv_bfloat16* an = Ap + (size_t)(kt + 1) * BK;
            const __nv_bfloat16* bn = Bp + (size_t)(kt + 1) * BK;
            pa0 = *(const uint4*)(an);
            pa1 = *(const uint4*)(an + 8);
            pb0 = *(const uint4*)(bn);
            pb1 = *(const uint4*)(bn + 8);
        }

        const uint32_t abuf = a_base + buf * (BUFH * 2);
        const uint32_t bbuf = b_base + buf * (BUFH * 2);
#pragma unroll
        for (int ks = 0; ks < 2; ++ks) {
            uint32_t a[4][4], b[4][2];
#pragma unroll
            for (int mi = 0; mi < 4; ++mi)
                ldmx4(a[mi][0], a[mi][1], a[mi][2], a[mi][3],
                      abuf + mi * 16 * (RS * 2) + ks * 32);
#pragma unroll
            for (int nb = 0; nb < 2; ++nb)
                ldmx4(b[nb * 2][0], b[nb * 2][1], b[nb * 2 + 1][0],
                      b[nb * 2 + 1][1],
                      bbuf + nb * 16 * (RS * 2) + ks * 32);
#pragma unroll
            for (int mi = 0; mi < 4; ++mi)
#pragma unroll
                for (int ni = 0; ni < 4; ++ni)
                    mma16816(acc[mi][ni], a[mi], b[ni]);
        }

        if (has_next) {
            const uint32_t nb = (buf ^ 1);
            *(uint4*)((char*)As + nb * (BUFH * 2) + sst)      = pa0;
            *(uint4*)((char*)As + nb * (BUFH * 2) + sst + 16) = pa1;
            *(uint4*)((char*)Bs + nb * (BUFH * 2) + sst)      = pb0;
            *(uint4*)((char*)Bs + nb * (BUFH * 2) + sst + 16) = pb1;
        }
        __syncthreads();
    }

#pragma unroll
    for (int ni = 0; ni < 4; ++ni) {
        const int col = n0 + wn + ni * 8 + tig * 2;
        const float2 bv = *(const float2*)&bias[col];
#pragma unroll
        for (int mi = 0; mi < 4; ++mi) {
            const int row = m0 + wm + mi * 16 + grp;
            float2 v0 = make_float2(acc[mi][ni][0] + bv.x, acc[mi][ni][1] + bv.y);
            float2 v1 = make_float2(acc[mi][ni][2] + bv.x, acc[mi][ni][3] + bv.y);
            *(float2*)&C[(size_t)row * N + col]       = v0;
            *(float2*)&C[(size_t)(row + 8) * N + col] = v1;
        }
    }
}

// ============================================================================
// Tensor-core fused attention.
// Block = (128-q-tile, h, b), 512 threads (16 warps).
// QK^T: bf16 split planes (Qh,Kh),(Ql,Kh),(Qh,Kl); dh=64 each.
// S fp32 -> +pp[cls], /32, classSum -> bf16 split Sh/Sl in smem.
// S@V: planes (Sh,Vh),(Sl,Vh),(Sh,Vl); V fragments via ldmatrix.trans.
// Epilogue: O += cs @ rel_v_table; write X.
// ============================================================================
#define QRS 72           // halves per row (Q/K/V planes); 144B, mod128=16
#define SRS 136          // halves per row (S planes); 272B, mod128=16
#define ATT_SMEM 212480

__global__ __launch_bounds__(512) void attn_mma(
    const float* __restrict__ Qg, const float* __restrict__ Kg,
    const float* __restrict__ Vg, const float* __restrict__ rkt,
    const float* __restrict__ rvt, float* __restrict__ X) {
    extern __shared__ char smc[];
    __nv_bfloat16* Qh = (__nv_bfloat16*)(smc);
    __nv_bfloat16* Ql = (__nv_bfloat16*)(smc + 18432);
    __nv_bfloat16* Kh = (__nv_bfloat16*)(smc + 36864);
    __nv_bfloat16* Kl = (__nv_bfloat16*)(smc + 55296);
    __nv_bfloat16* Vh = (__nv_bfloat16*)(smc + 73728);
    __nv_bfloat16* Vl = (__nv_bfloat16*)(smc + 92160);
    __nv_bfloat16* Sh = (__nv_bfloat16*)(smc + 110592);
    __nv_bfloat16* Sl = (__nv_bfloat16*)(smc + 145408);
    float* rk = (float*)(smc + 180224);
    float* rv = (float*)(smc + 185600);
    float* pp = (float*)(smc + 190976);
    float* cs = (float*)(smc + 201728);

    const uint32_t sQh = smem_u32(Qh), sQl = smem_u32(Ql);
    const uint32_t sKh = smem_u32(Kh), sKl = smem_u32(Kl);
    const uint32_t sVh = smem_u32(Vh), sVl = smem_u32(Vl);
    const uint32_t sSh = smem_u32(Sh), sSl = smem_u32(Sl);

    const int t = threadIdx.x;
    const int lane = t & 31;
    const int w = t >> 5;
    const int grp = lane >> 2;
    const int tig = lane & 3;
    const int q0 = blockIdx.x * 128;
    const int h = blockIdx.y;
    const int b = blockIdx.z;

    const float* Qb = Qg + ((size_t)b * SS + q0) * DMOD + h * DH;
    const float* Kb = Kg + (size_t)b * SS * DMOD + h * DH;
    const float* Vb = Vg + (size_t)b * SS * DMOD + h * DH;

    // ---- load Q tile, split -> Qh/Ql ----
    {
        const int row = t >> 2;
        const int c0 = (t & 3) * 16;
        const float* src = Qb + (size_t)row * DMOD + c0;
#pragma unroll
        for (int i = 0; i < 4; ++i)
            split_store4(*(const float4*)(src + i * 4), Qh, Ql,
                         row * QRS + c0 + i * 4);
    }
    for (int i = t; i < NR * 64; i += 512) { rk[i] = rkt[i]; rv[i] = rvt[i]; }
    for (int i = t; i < 128 * NR; i += 512) cs[i] = 0.f;
    __syncthreads();

    // ---- pp[q][j] = Q[q].rel_k[j] (reconstructed Q = Qh+Ql) ----
    for (int e = t; e < 128 * NR; e += 512) {
        int qq = e / NR, j = e - qq * NR;
        float s = 0.f;
#pragma unroll 16
        for (int d = 0; d < 64; ++d)
            s += (__bfloat162float(Qh[qq * QRS + d]) +
                  __bfloat162float(Ql[qq * QRS + d])) * rk[j * 64 + d];
        pp[e] = s;
    }

    float o[4][4];
#pragma unroll
    for (int ni = 0; ni < 4; ++ni)
#pragma unroll
        for (int r = 0; r < 4; ++r) o[ni][r] = 0.f;

    const int wq = w & 3, wk = w >> 2;       // QK^T: 4x4 warps, 32x32 each
    const int wq2 = w >> 1, wd = w & 1;      // S@V: 8x2 warps, 16x32 each

    for (int kt = 0; kt < 8; ++kt) {
        const int k0 = kt * 128;
        __syncthreads();   // prev iter's K/V/S fully consumed; pp/cs visible at kt=0

        // ---- load K,V tiles, split ----
        {
            const int sel = t >> 8;                  // 0:K 1:V
            const int r = (t & 255) >> 1;
            const int c0 = (t & 1) * 32;
            const float* src =
                (sel ? Vb : Kb) + (size_t)(k0 + r) * DMOD + c0;
            __nv_bfloat16* Hp = sel ? Vh : Kh;
            __nv_bfloat16* Lp = sel ? Vl : Kl;
#pragma unroll
            for (int i = 0; i < 8; ++i)
                split_store4(*(const float4*)(src + i * 4), Hp, Lp,
                             r * QRS + c0 + i * 4);
        }
        __syncthreads();

        // ---- S = Q K^T over 3 split planes ----
        float s[2][4][4];
#pragma unroll
        for (int mi = 0; mi < 2; ++mi)
#pragma unroll
            for (int ni = 0; ni < 4; ++ni)
#pragma unroll
                for (int r = 0; r < 4; ++r) s[mi][ni][r] = 0.f;

        const uint32_t qpl[3] = {sQh, sQl, sQh};
        const uint32_t kpl[3] = {sKh, sKh, sKl};
        const uint32_t a_off = (wq * 32 + (lane & 15)) * (QRS * 2) +
                               ((lane >> 4) * 8) * 2;
        const uint32_t b_off =
            (wk * 32 + (lane & 7) + ((lane >> 4) & 1) * 8) * (QRS * 2) +
            (((lane >> 3) & 1) * 8) * 2;
#pragma unroll
        for (int p = 0; p < 3; ++p) {
#pragma unroll
            for (int ks = 0; ks < 4; ++ks) {
                uint32_t a[2][4], bb[4][2];
#pragma unroll
                for (int mi = 0; mi < 2; ++mi)
                    ldmx4(a[mi][0], a[mi][1], a[mi][2], a[mi][3],
                          qpl[p] + a_off + mi * 16 * (QRS * 2) + ks * 32);
#pragma unroll
                for (int nb = 0; nb < 2; ++nb)
                    ldmx4(bb[nb * 2][0], bb[nb * 2][1], bb[nb * 2 + 1][0],
                          bb[nb * 2 + 1][1],
                          kpl[p] + b_off + nb * 16 * (QRS * 2) + ks * 32);
#pragma unroll
                for (int mi = 0; mi < 2; ++mi)
#pragma unroll
                    for (int ni = 0; ni < 4; ++ni)
                        mma16816(s[mi][ni], a[mi], bb[ni]);
            }
        }

        // ---- post-process: + pp[cls], scale, classSum, split-store S ----
        float l0[4] = {0.f, 0.f, 0.f, 0.f};
        float l20[4] = {0.f, 0.f, 0.f, 0.f};
#pragma unroll
        for (int mi = 0; mi < 2; ++mi) {
#pragma unroll
            for (int half = 0; half < 2; ++half) {
                const int row = wq * 32 + mi * 16 + grp + half * 8;
                const int gq = q0 + row;
                const float* ppr = pp + row * NR;
                const int li = mi * 2 + half;
#pragma unroll
                for (int ni = 0; ni < 4; ++ni) {
                    const int col = wk * 32 + ni * 8 + tig * 2;
                    const int d0 = k0 + col - gq;
                    const int d1 = d0 + 1;
                    const int c0 = d0 < -10 ? 0 : (d0 > 10 ? 20 : d0 + 10);
                    const int c1 = d1 < -10 ? 0 : (d1 > 10 ? 20 : d1 + 10);
                    const float f0 = (s[mi][ni][half * 2 + 0] + ppr[c0]) * 0.03125f;
                    const float f1 = (s[mi][ni][half * 2 + 1] + ppr[c1]) * 0.03125f;
                    if (d0 <= -10)      l0[li]  += f0;
                    else if (d0 >= 10)  l20[li] += f0;
                    else                cs[row * NR + d0 + 10] += f0;
                    if (d1 <= -10)      l0[li]  += f1;
                    else if (d1 >= 10)  l20[li] += f1;
                    else                cs[row * NR + d1 + 10] += f1;
                    __nv_bfloat16 h0 = __float2bfloat16_rn(f0);
                    __nv_bfloat16 h1 = __float2bfloat16_rn(f1);
                    __nv_bfloat16 lo0 = __float2bfloat16_rn(f0 - __bfloat162float(h0));
                    __nv_bfloat16 lo1 = __float2bfloat16_rn(f1 - __bfloat162float(h1));
                    *(__nv_bfloat162*)(Sh + row * SRS + col) = __halves2bfloat162(h0, h1);
                    *(__nv_bfloat162*)(Sl + row * SRS + col) = __halves2bfloat162(lo0, lo1);
                }
            }
        }
#pragma unroll
        for (int li = 0; li < 4; ++li) {
            const int row = wq * 32 + (li >> 1) * 16 + grp + (li & 1) * 8;
            atomicAdd(&cs[row * NR + 0], l0[li]);
            atomicAdd(&cs[row * NR + 20], l20[li]);
        }
        __syncthreads();

        // ---- O += S @ V over 3 split planes (V via ldmatrix.trans) ----
        const uint32_t spl[3] = {sSh, sSl, sSh};
        const uint32_t vpl[3] = {sVh, sVh, sVl};
        const uint32_t sa_off = (wq2 * 16 + (lane & 15)) * (SRS * 2) +
                                ((lane >> 4) * 8) * 2;
        const uint32_t vb_off_row = ((lane & 7) + ((lane >> 3) & 1) * 8);
        const uint32_t vb_off_col = (wd * 32 + (lane >> 4) * 8) * 2;
#pragma unroll
        for (int p = 0; p < 3; ++p) {
#pragma unroll
            for (int ks = 0; ks < 8; ++ks) {
                uint32_t a[4], bb[4][2];
                ldmx4(a[0], a[1], a[2], a[3], spl[p] + sa_off + ks * 32);
#pragma unroll
                for (int nb = 0; nb < 2; ++nb)
                    ldmx4t(bb[nb * 2][0], bb[nb * 2][1], bb[nb * 2 + 1][0],
                           bb[nb * 2 + 1][1],
                           vpl[p] + (ks * 16 + vb_off_row) * (QRS * 2) +
                               vb_off_col + nb * 32);
#pragma unroll
                for (int ni = 0; ni < 4; ++ni)
                    mma16816(o[ni], a, bb[ni]);
            }
        }
    }
    __syncthreads();   // cs complete

    // ---- epilogue: O += cs @ rel_v_table; write X ----
#pragma unroll
    for (int ni = 0; ni < 4; ++ni) {
#pragma unroll
        for (int half = 0; half < 2; ++half) {
            const int row = wq2 * 16 + grp + half * 8;
            const int col = wd * 32 + ni * 8 + tig * 2;
            float a0 = o[ni][half * 2 + 0];
            float a1 = o[ni][half * 2 + 1];
            const float* csr = cs + row * NR;
#pragma unroll
            for (int j = 0; j < NR; ++j) {
                const float c = csr[j];
                a0 += c * rv[j * 64 + col];
                a1 += c * rv[j * 64 + col + 1];
            }
            float* dst = X + ((size_t)b * SS + q0 + row) * DMOD + h * DH + col;
            *(float2*)dst = make_float2(a0, a1);
        }
    }
}

// ============================================================================
// launch
// ============================================================================
extern "C" void kernel_launch(void* const* d_in, const int* in_sizes, int n_in,
                              void* d_out, int out_size) {
    const float* q   = (const float*)d_in[0];
    const float* k   = (const float*)d_in[1];
    const float* v   = (const float*)d_in[2];
    const float* Wq  = (const float*)d_in[4];
    const float* bq  = (const float*)d_in[5];
    const float* Wk  = (const float*)d_in[6];
    const float* bk  = (const float*)d_in[7];
    const float* Wv  = (const float*)d_in[8];
    const float* bv  = (const float*)d_in[9];
    const float* W0  = (const float*)d_in[10];
    const float* b0  = (const float*)d_in[11];
    const float* rkt = (const float*)d_in[12];
    const float* rvt = (const float*)d_in[13];

    float *Qp, *Kp, *Vp, *Xp;
    cudaGetSymbolAddress((void**)&Qp, g_Q);
    cudaGetSymbolAddress((void**)&Kp, g_K);
    cudaGetSymbolAddress((void**)&Vp, g_V);
    cudaGetSymbolAddress((void**)&Xp, g_X);
    __nv_bfloat16 *q2, *k2, *v2, *x2, *wq2, *wk2, *wv2, *w02;
    cudaGetSymbolAddress((void**)&q2, g_q2);
    cudaGetSymbolAddress((void**)&k2, g_k2);
    cudaGetSymbolAddress((void**)&v2, g_v2);
    cudaGetSymbolAddress((void**)&x2, g_x2);
    cudaGetSymbolAddress((void**)&wq2, g_wq2);
    cudaGetSymbolAddress((void**)&wk2, g_wk2);
    cudaGetSymbolAddress((void**)&wv2, g_wv2);
    cudaGetSymbolAddress((void**)&w02, g_w02);

    const int M = BB * SS;          // 2048
    const int NACT = M * DMOD;      // 2M elements
    const int NW = DMOD * DMOD;     // 1M elements

    // batched splits: acts (q,k,v) and weights (Wq,Wk,Wv,W0)
    SplitPack ap;
    ap.in[0] = q;  ap.out[0] = q2;
    ap.in[1] = k;  ap.out[1] = k2;
    ap.in[2] = v;  ap.out[2] = v2;
    ap.in[3] = q;  ap.out[3] = q2;   // unused
    split_multi<<<dim3(NACT / 256, 3), 256>>>(ap, NACT, 1);
    SplitPack wp;
    wp.in[0] = Wq; wp.out[0] = wq2;
    wp.in[1] = Wk; wp.out[1] = wk2;
    wp.in[2] = Wv; wp.out[2] = wv2;
    wp.in[3] = W0; wp.out[3] = w02;
    split_multi<<<dim3(NW / 256, 4), 256>>>(wp, NW, 0);

    // fused q/k/v projections
    GemmArgs pa;
    pa.A[0] = q2;  pa.A[1] = k2;  pa.A[2] = v2;
    pa.B[0] = wq2; pa.B[1] = wk2; pa.B[2] = wv2;
    pa.bias[0] = bq; pa.bias[1] = bk; pa.bias[2] = bv;
    pa.C[0] = Qp; pa.C[1] = Kp; pa.C[2] = Vp;
    gemm_mma<<<dim3(DMOD / 128, M / 128, 3), 256>>>(pa, DMOD);

    // tensor-core fused attention
    cudaFuncSetAttribute(attn_mma,
                         cudaFuncAttributeMaxDynamicSharedMemorySize, ATT_SMEM);
    attn_mma<<<dim3(SS / 128, HH, BB), 512, ATT_SMEM>>>(Qp, Kp, Vp, rkt, rvt, Xp);

    // output projection
    SplitPack xp;
    xp.in[0] = Xp; xp.out[0] = x2;
    xp.in[1] = Xp; xp.out[1] = x2;
    xp.in[2] = Xp; xp.out[2] = x2;
    xp.in[3] = Xp; xp.out[3] = x2;
    split_multi<<<dim3(NACT / 256, 1), 256>>>(xp, NACT, 1);
    GemmArgs oa;
    oa.A[0] = x2;  oa.A[1] = x2;  oa.A[2] = x2;
    oa.B[0] = w02; oa.B[1] = w02; oa.B[2] = w02;
    oa.bias[0] = b0; oa.bias[1] = b0; oa.bias[2] = b0;
    oa.C[0] = (float*)d_out; oa.C[1] = (float*)d_out; oa.C[2] = (float*)d_out;
    gemm_mma<<<dim3(DMOD / 128, M / 128, 1), 256>>>(oa, DMOD);
}

// round 6
// speedup vs baseline: 1.5147x; 1.0301x over previous
#include <cuda_runtime.h>
#include <cuda_bf16.h>
#include <cstdint>

#define BB 2
#define SS 1024
#define DMOD 1024
#define HH 16
#define DH 64
#define NR 21     // 2*MAX_REL+1
#define K3 3072   // 3 * DMOD (split-concatenated K)

// ============================================================================
// scratch (static device globals: no allocations allowed)
// ============================================================================
// pre-split projection outputs (hi/lo bf16 planes, row-major [B*S, DMOD])
__device__ __nv_bfloat16 g_Qh[BB * SS * DMOD];
__device__ __nv_bfloat16 g_Ql[BB * SS * DMOD];
__device__ __nv_bfloat16 g_Kh[BB * SS * DMOD];
__device__ __nv_bfloat16 g_Kl[BB * SS * DMOD];
__device__ __nv_bfloat16 g_Vh[BB * SS * DMOD];
__device__ __nv_bfloat16 g_Vl[BB * SS * DMOD];

// split-concatenated bf16 operands, row-major [rows, K3]
__device__ __nv_bfloat16 g_q2[BB * SS * K3];
__device__ __nv_bfloat16 g_k2[BB * SS * K3];
__device__ __nv_bfloat16 g_v2[BB * SS * K3];
__device__ __nv_bfloat16 g_x2[BB * SS * K3];
__device__ __nv_bfloat16 g_wq2[DMOD * K3];
__device__ __nv_bfloat16 g_wk2[DMOD * K3];
__device__ __nv_bfloat16 g_wv2[DMOD * K3];
__device__ __nv_bfloat16 g_w02[DMOD * K3];

// ============================================================================
// batched split kernel: fp32 -> bf16 hi/lo, written K-concatenated.
//   act  (A-side): [0,K)=hi  [K,2K)=lo  [2K,3K)=hi
//   wt   (B-side): [0,K)=hi  [K,2K)=hi  [2K,3K)=lo
// ============================================================================
struct SplitPack {
    const float* in[4];
    __nv_bfloat16* out[4];
};

__global__ __launch_bounds__(256) void split_multi(SplitPack p, int n, int is_act) {
    int i = blockIdx.x * blockDim.x + threadIdx.x;
    if (i >= n) return;
    const float* in = p.in[blockIdx.y];
    __nv_bfloat16* out = p.out[blockIdx.y];
    int m = i >> 10;          // K = 1024
    int k = i & 1023;
    float x = in[i];
    __nv_bfloat16 h = __float2bfloat16_rn(x);
    float r = x - __bfloat162float(h);
    __nv_bfloat16 l = __float2bfloat16_rn(r);
    size_t base = (size_t)m * K3 + k;
    out[base] = h;
    if (is_act) {
        out[base + 1024] = l;
        out[base + 2048] = h;
    } else {
        out[base + 1024] = h;
        out[base + 2048] = l;
    }
}

// ============================================================================
// mma.sync helpers
// ============================================================================
__device__ __forceinline__ uint32_t smem_u32(const void* p) {
    uint32_t a;
    asm("{ .reg .u64 t; cvta.to.shared.u64 t, %1; cvt.u32.u64 %0, t; }"
        : "=r"(a) : "l"(p));
    return a;
}

__device__ __forceinline__ void ldmx4(uint32_t& r0, uint32_t& r1,
                                      uint32_t& r2, uint32_t& r3,
                                      uint32_t addr) {
    asm volatile(
        "ldmatrix.sync.aligned.m8n8.x4.shared.b16 {%0,%1,%2,%3}, [%4];"
        : "=r"(r0), "=r"(r1), "=r"(r2), "=r"(r3) : "r"(addr));
}

__device__ __forceinline__ void ldmx4t(uint32_t& r0, uint32_t& r1,
                                       uint32_t& r2, uint32_t& r3,
                                       uint32_t addr) {
    asm volatile(
        "ldmatrix.sync.aligned.m8n8.x4.trans.shared.b16 {%0,%1,%2,%3}, [%4];"
        : "=r"(r0), "=r"(r1), "=r"(r2), "=r"(r3) : "r"(addr));
}

__device__ __forceinline__ void mma16816(float* c, const uint32_t* a,
                                         const uint32_t* b) {
    asm volatile(
        "mma.sync.aligned.m16n8k16.row.col.f32.bf16.bf16.f32 "
        "{%0,%1,%2,%3}, {%4,%5,%6,%7}, {%8,%9}, {%0,%1,%2,%3};"
        : "+f"(c[0]), "+f"(c[1]), "+f"(c[2]), "+f"(c[3])
        : "r"(a[0]), "r"(a[1]), "r"(a[2]), "r"(a[3]), "r"(b[0]), "r"(b[1]));
}

// fp32 -> (hi, lo) bf16
__device__ __forceinline__ void split2(float x, __nv_bfloat16& h, __nv_bfloat16& l) {
    h = __float2bfloat16_rn(x);
    l = __float2bfloat16_rn(x - __bfloat162float(h));
}

// ============================================================================
// bf16 HMMA GEMM over K3.
// mode 0: C fp32 = acc + bias.
// mode 1: write split bf16 hi/lo planes (Ch, Cl) = split(acc + bias).
// ============================================================================
struct GemmArgs {
    const __nv_bfloat16* A[3];
    const __nv_bfloat16* B[3];
    const float* bias[3];
    float* C[3];
    __nv_bfloat16* Ch[3];
    __nv_bfloat16* Cl[3];
    int mode;
};

#define BK 32
#define RS 40
#define BUFH (128 * RS)

__global__ __launch_bounds__(256) void gemm_mma(GemmArgs ga, int N) {
    __shared__ __align__(16) __nv_bfloat16 As[2][BUFH];
    __shared__ __align__(16) __nv_bfloat16 Bs[2][BUFH];

    const int t = threadIdx.x;
    const int lane = t & 31;
    const int wid = t >> 5;
    const int wm = (wid & 1) * 64;
    const int wn = (wid >> 1) * 32;
    const int grp = lane >> 2;
    const int tig = lane & 3;
    const int z = blockIdx.z;
    const int m0 = blockIdx.y * 128;
    const int n0 = blockIdx.x * 128;

    const __nv_bfloat16* Ag = ga.A[z];
    const __nv_bfloat16* Bg = ga.B[z];
    const float* bias = ga.bias[z];

    const int lrow = t >> 1;
    const int lcol = (t & 1) * 16;
    const __nv_bfloat16* Ap = Ag + (size_t)(m0 + lrow) * K3 + lcol;
    const __nv_bfloat16* Bp = Bg + (size_t)(n0 + lrow) * K3 + lcol;
    const uint32_t sst = lrow * (RS * 2) + lcol * 2;

    const uint32_t asb = smem_u32(As);
    const uint32_t bsb = smem_u32(Bs);

    const uint32_t a_row = wm + (lane & 15);
    const uint32_t a_k   = (lane >> 4) * 8;
    const uint32_t a_base = asb + a_row * (RS * 2) + a_k * 2;
    const uint32_t b_row = wn + (lane & 7) + ((lane >> 4) & 1) * 8;
    const uint32_t b_k   = ((lane >> 3) & 1) * 8;
    const uint32_t b_base = bsb + b_row * (RS * 2) + b_k * 2;

    float acc[4][4][4];
#pragma unroll
    for (int mi = 0; mi < 4; ++mi)
#pragma unroll
        for (int ni = 0; ni < 4; ++ni)
#pragma unroll
            for (int r = 0; r < 4; ++r) acc[mi][ni][r] = 0.f;

    uint4 pa0 = *(const uint4*)(Ap);
    uint4 pa1 = *(const uint4*)(Ap + 8);
    uint4 pb0 = *(const uint4*)(Bp);
    uint4 pb1 = *(const uint4*)(Bp + 8);
    *(uint4*)((char*)As + sst)      = pa0;
    *(uint4*)((char*)As + sst + 16) = pa1;
    *(uint4*)((char*)Bs + sst)      = pb0;
    *(uint4*)((char*)Bs + sst + 16) = pb1;
    __syncthreads();

    const int NT = K3 / BK;
    for (int kt = 0; kt < NT; ++kt) {
        const int buf = kt & 1;
        const bool has_next = (kt + 1 < NT);
        if (has_next) {
            const __nv_bfloat16* an = Ap + (size_t)(kt + 1) * BK;
            const __nv_bfloat16* bn = Bp + (size_t)(kt + 1) * BK;
            pa0 = *(const uint4*)(an);
            pa1 = *(const uint4*)(an + 8);
            pb0 = *(const uint4*)(bn);
            pb1 = *(const uint4*)(bn + 8);
        }

        const uint32_t abuf = a_base + buf * (BUFH * 2);
        const uint32_t bbuf = b_base + buf * (BUFH * 2);
#pragma unroll
        for (int ks = 0; ks < 2; ++ks) {
            uint32_t a[4][4], b[4][2];
#pragma unroll
            for (int mi = 0; mi < 4; ++mi)
                ldmx4(a[mi][0], a[mi][1], a[mi][2], a[mi][3],
                      abuf + mi * 16 * (RS * 2) + ks * 32);
#pragma unroll
            for (int nb = 0; nb < 2; ++nb)
                ldmx4(b[nb * 2][0], b[nb * 2][1], b[nb * 2 + 1][0],
                      b[nb * 2 + 1][1],
                      bbuf + nb * 16 * (RS * 2) + ks * 32);
#pragma unroll
            for (int mi = 0; mi < 4; ++mi)
#pragma unroll
                for (int ni = 0; ni < 4; ++ni)
                    mma16816(acc[mi][ni], a[mi], b[ni]);
        }

        if (has_next) {
            const uint32_t nb = (buf ^ 1);
            *(uint4*)((char*)As + nb * (BUFH * 2) + sst)      = pa0;
            *(uint4*)((char*)As + nb * (BUFH * 2) + sst + 16) = pa1;
            *(uint4*)((char*)Bs + nb * (BUFH * 2) + sst)      = pb0;
            *(uint4*)((char*)Bs + nb * (BUFH * 2) + sst + 16) = pb1;
        }
        __syncthreads();
    }

    if (ga.mode == 0) {
        float* C = ga.C[z];
#pragma unroll
        for (int ni = 0; ni < 4; ++ni) {
            const int col = n0 + wn + ni * 8 + tig * 2;
            const float2 bv = *(const float2*)&bias[col];
#pragma unroll
            for (int mi = 0; mi < 4; ++mi) {
                const int row = m0 + wm + mi * 16 + grp;
                float2 v0 = make_float2(acc[mi][ni][0] + bv.x, acc[mi][ni][1] + bv.y);
                float2 v1 = make_float2(acc[mi][ni][2] + bv.x, acc[mi][ni][3] + bv.y);
                *(float2*)&C[(size_t)row * N + col]       = v0;
                *(float2*)&C[(size_t)(row + 8) * N + col] = v1;
            }
        }
    } else {
        __nv_bfloat16* Ch = ga.Ch[z];
        __nv_bfloat16* Cl = ga.Cl[z];
#pragma unroll
        for (int ni = 0; ni < 4; ++ni) {
            const int col = n0 + wn + ni * 8 + tig * 2;
            const float2 bv = *(const float2*)&bias[col];
#pragma unroll
            for (int mi = 0; mi < 4; ++mi) {
                const int row = m0 + wm + mi * 16 + grp;
                float f00 = acc[mi][ni][0] + bv.x, f01 = acc[mi][ni][1] + bv.y;
                float f10 = acc[mi][ni][2] + bv.x, f11 = acc[mi][ni][3] + bv.y;
                __nv_bfloat16 h00, l00, h01, l01, h10, l10, h11, l11;
                split2(f00, h00, l00);
                split2(f01, h01, l01);
                split2(f10, h10, l10);
                split2(f11, h11, l11);
                const size_t i0 = (size_t)row * N + col;
                const size_t i1 = (size_t)(row + 8) * N + col;
                *(__nv_bfloat162*)(Ch + i0) = __halves2bfloat162(h00, h01);
                *(__nv_bfloat162*)(Cl + i0) = __halves2bfloat162(l00, l01);
                *(__nv_bfloat162*)(Ch + i1) = __halves2bfloat162(h10, h11);
                *(__nv_bfloat162*)(Cl + i1) = __halves2bfloat162(l10, l11);
            }
        }
    }
}

// ============================================================================
// Tensor-core fused attention, pre-split operands.
// Block = (128-q-tile, h, b), 512 threads (16 warps).
// Loads Qh/Ql/Kh/Kl/Vh/Vl bf16 planes directly (pure copies, no cvt).
// QK^T planes (Qh,Kh),(Ql,Kh),(Qh,Kl); S postprocess; S@V planes
// (Sh,Vh),(Sl,Vh),(Sh,Vl) with V via ldmatrix.trans.
// Output written directly in split-concat x2 layout (hi | lo | hi).
// ============================================================================
#define QRS 72           // halves per row (Q/K/V planes); 144B
#define SRS 136          // halves per row (S planes); 272B
#define ATT_SMEM 212480

__global__ __launch_bounds__(512) void attn_mma(
    const __nv_bfloat16* __restrict__ Qhg, const __nv_bfloat16* __restrict__ Qlg,
    const __nv_bfloat16* __restrict__ Khg, const __nv_bfloat16* __restrict__ Klg,
    const __nv_bfloat16* __restrict__ Vhg, const __nv_bfloat16* __restrict__ Vlg,
    const float* __restrict__ rkt, const float* __restrict__ rvt,
    __nv_bfloat16* __restrict__ x2) {
    extern __shared__ char smc[];
    __nv_bfloat16* Qh = (__nv_bfloat16*)(smc);
    __nv_bfloat16* Ql = (__nv_bfloat16*)(smc + 18432);
    __nv_bfloat16* Kh = (__nv_bfloat16*)(smc + 36864);
    __nv_bfloat16* Kl = (__nv_bfloat16*)(smc + 55296);
    __nv_bfloat16* Vh = (__nv_bfloat16*)(smc + 73728);
    __nv_bfloat16* Vl = (__nv_bfloat16*)(smc + 92160);
    __nv_bfloat16* Sh = (__nv_bfloat16*)(smc + 110592);
    __nv_bfloat16* Sl = (__nv_bfloat16*)(smc + 145408);
    float* rk = (float*)(smc + 180224);
    float* rv = (float*)(smc + 185600);
    float* pp = (float*)(smc + 190976);
    float* cs = (float*)(smc + 201728);

    const uint32_t sQh = smem_u32(Qh), sQl = smem_u32(Ql);
    const uint32_t sKh = smem_u32(Kh), sKl = smem_u32(Kl);
    const uint32_t sVh = smem_u32(Vh), sVl = smem_u32(Vl);
    const uint32_t sSh = smem_u32(Sh), sSl = smem_u32(Sl);

    const int t = threadIdx.x;
    const int lane = t & 31;
    const int w = t >> 5;
    const int grp = lane >> 2;
    const int tig = lane & 3;
    const int q0 = blockIdx.x * 128;
    const int h = blockIdx.y;
    const int b = blockIdx.z;

    const size_t hoff = (size_t)h * DH;

    // ---- load Q planes (pure copies: 64 bf16 = 8 x uint4 per row) ----
    if (t < 256) {
        const int pl = t >> 7;            // 0: hi, 1: lo
        const int r = t & 127;
        const __nv_bfloat16* src =
            (pl ? Qlg : Qhg) + ((size_t)b * SS + q0 + r) * DMOD + hoff;
        __nv_bfloat16* dst = (pl ? Ql : Qh) + r * QRS;
#pragma unroll
        for (int i = 0; i < 8; ++i)
            *(uint4*)(dst + i * 8) = *(const uint4*)(src + i * 8);
    }
    for (int i = t; i < NR * 64; i += 512) { rk[i] = rkt[i]; rv[i] = rvt[i]; }
    for (int i = t; i < 128 * NR; i += 512) cs[i] = 0.f;
    __syncthreads();

    // ---- pp[q][j] = Q[q].rel_k[j] (Q = Qh + Ql) ----
    for (int e = t; e < 128 * NR; e += 512) {
        int qq = e / NR, j = e - qq * NR;
        float s = 0.f;
#pragma unroll 16
        for (int d = 0; d < 64; ++d)
            s += (__bfloat162float(Qh[qq * QRS + d]) +
                  __bfloat162float(Ql[qq * QRS + d])) * rk[j * 64 + d];
        pp[e] = s;
    }

    float o[4][4];
#pragma unroll
    for (int ni = 0; ni < 4; ++ni)
#pragma unroll
        for (int r = 0; r < 4; ++r) o[ni][r] = 0.f;

    const int wq = w & 3, wk = w >> 2;       // QK^T: 4x4 warps, 32x32 each
    const int wq2 = w >> 1, wd = w & 1;      // S@V: 8x2 warps, 16x32 each

    // per-thread K/V plane copy setup
    const int kvpl = t >> 7;                 // 0:Kh 1:Kl 2:Vh 3:Vl
    const int kvr = t & 127;
    const __nv_bfloat16* kvsrc0 =
        (kvpl == 0 ? Khg : kvpl == 1 ? Klg : kvpl == 2 ? Vhg : Vlg) +
        ((size_t)b * SS + kvr) * DMOD + hoff;
    __nv_bfloat16* kvdst =
        (kvpl == 0 ? Kh : kvpl == 1 ? Kl : kvpl == 2 ? Vh : Vl) + kvr * QRS;

    for (int kt = 0; kt < 8; ++kt) {
        const int k0 = kt * 128;
        __syncthreads();   // prev iter fully consumed; pp/cs visible at kt=0

        // ---- load K,V planes (pure copies) ----
        {
            const __nv_bfloat16* src = kvsrc0 + (size_t)k0 * DMOD;
#pragma unroll
            for (int i = 0; i < 8; ++i)
                *(uint4*)(kvdst + i * 8) = *(const uint4*)(src + i * 8);
        }
        __syncthreads();

        // ---- S = Q K^T over 3 split planes ----
        float s[2][4][4];
#pragma unroll
        for (int mi = 0; mi < 2; ++mi)
#pragma unroll
            for (int ni = 0; ni < 4; ++ni)
#pragma unroll
                for (int r = 0; r < 4; ++r) s[mi][ni][r] = 0.f;

        const uint32_t qpl[3] = {sQh, sQl, sQh};
        const uint32_t kpl[3] = {sKh, sKh, sKl};
        const uint32_t a_off = (wq * 32 + (lane & 15)) * (QRS * 2) +
                               ((lane >> 4) * 8) * 2;
        const uint32_t b_off =
            (wk * 32 + (lane & 7) + ((lane >> 4) & 1) * 8) * (QRS * 2) +
            (((lane >> 3) & 1) * 8) * 2;
#pragma unroll
        for (int p = 0; p < 3; ++p) {
#pragma unroll
            for (int ks = 0; ks < 4; ++ks) {
                uint32_t a[2][4], bb[4][2];
#pragma unroll
                for (int mi = 0; mi < 2; ++mi)
                    ldmx4(a[mi][0], a[mi][1], a[mi][2], a[mi][3],
                          qpl[p] + a_off + mi * 16 * (QRS * 2) + ks * 32);
#pragma unroll
                for (int nb = 0; nb < 2; ++nb)
                    ldmx4(bb[nb * 2][0], bb[nb * 2][1], bb[nb * 2 + 1][0],
                          bb[nb * 2 + 1][1],
                          kpl[p] + b_off + nb * 16 * (QRS * 2) + ks * 32);
#pragma unroll
                for (int mi = 0; mi < 2; ++mi)
#pragma unroll
                    for (int ni = 0; ni < 4; ++ni)
                        mma16816(s[mi][ni], a[mi], bb[ni]);
            }
        }

        // ---- post-process: + pp[cls], scale, classSum, split-store S ----
        float l0[4] = {0.f, 0.f, 0.f, 0.f};
        float l20[4] = {0.f, 0.f, 0.f, 0.f};
#pragma unroll
        for (int mi = 0; mi < 2; ++mi) {
#pragma unroll
            for (int half = 0; half < 2; ++half) {
                const int row = wq * 32 + mi * 16 + grp + half * 8;
                const int gq = q0 + row;
                const float* ppr = pp + row * NR;
                const int li = mi * 2 + half;
#pragma unroll
                for (int ni = 0; ni < 4; ++ni) {
                    const int col = wk * 32 + ni * 8 + tig * 2;
                    const int d0 = k0 + col - gq;
                    const int d1 = d0 + 1;
                    const int c0 = d0 < -10 ? 0 : (d0 > 10 ? 20 : d0 + 10);
                    const int c1 = d1 < -10 ? 0 : (d1 > 10 ? 20 : d1 + 10);
                    const float f0 = (s[mi][ni][half * 2 + 0] + ppr[c0]) * 0.03125f;
                    const float f1 = (s[mi][ni][half * 2 + 1] + ppr[c1]) * 0.03125f;
                    if (d0 <= -10)      l0[li]  += f0;
                    else if (d0 >= 10)  l20[li] += f0;
                    else                cs[row * NR + d0 + 10] += f0;
                    if (d1 <= -10)      l0[li]  += f1;
                    else if (d1 >= 10)  l20[li] += f1;
                    else                cs[row * NR + d1 + 10] += f1;
                    __nv_bfloat16 h0, lo0, h1, lo1;
                    split2(f0, h0, lo0);
                    split2(f1, h1, lo1);
                    *(__nv_bfloat162*)(Sh + row * SRS + col) = __halves2bfloat162(h0, h1);
                    *(__nv_bfloat162*)(Sl + row * SRS + col) = __halves2bfloat162(lo0, lo1);
                }
            }
        }
#pragma unroll
        for (int li = 0; li < 4; ++li) {
            const int row = wq * 32 + (li >> 1) * 16 + grp + (li & 1) * 8;
            atomicAdd(&cs[row * NR + 0], l0[li]);
            atomicAdd(&cs[row * NR + 20], l20[li]);
        }
        __syncthreads();

        // ---- O += S @ V over 3 split planes (V via ldmatrix.trans) ----
        const uint32_t spl[3] = {sSh, sSl, sSh};
        const uint32_t vpl[3] = {sVh, sVh, sVl};
        const uint32_t sa_off = (wq2 * 16 + (lane & 15)) * (SRS * 2) +
                                ((lane >> 4) * 8) * 2;
        const uint32_t vb_off_row = ((lane & 7) + ((lane >> 3) & 1) * 8);
        const uint32_t vb_off_col = (wd * 32 + (lane >> 4) * 8) * 2;
#pragma unroll
        for (int p = 0; p < 3; ++p) {
#pragma unroll
            for (int ks = 0; ks < 8; ++ks) {
                uint32_t a[4], bb[4][2];
                ldmx4(a[0], a[1], a[2], a[3], spl[p] + sa_off + ks * 32);
#pragma unroll
                for (int nb = 0; nb < 2; ++nb)
                    ldmx4t(bb[nb * 2][0], bb[nb * 2][1], bb[nb * 2 + 1][0],
                           bb[nb * 2 + 1][1],
                           vpl[p] + (ks * 16 + vb_off_row) * (QRS * 2) +
                               vb_off_col + nb * 32);
#pragma unroll
                for (int ni = 0; ni < 4; ++ni)
                    mma16816(o[ni], a, bb[ni]);
            }
        }
    }
    __syncthreads();   // cs complete

    // ---- epilogue: O += cs @ rel_v_table; write x2 (hi | lo | hi) ----
#pragma unroll
    for (int ni = 0; ni < 4; ++ni) {
#pragma unroll
        for (int half = 0; half < 2; ++half) {
            const int row = wq2 * 16 + grp + half * 8;
            const int col = wd * 32 + ni * 8 + tig * 2;
            float a0 = o[ni][half * 2 + 0];
            float a1 = o[ni][half * 2 + 1];
            const float* csr = cs + row * NR;
#pragma unroll
            for (int j = 0; j < NR; ++j) {
                const float c = csr[j];
                a0 += c * rv[j * 64 + col];
                a1 += c * rv[j * 64 + col + 1];
            }
            __nv_bfloat16 h0, l0b, h1, l1b;
            split2(a0, h0, l0b);
            split2(a1, h1, l1b);
            const size_t base = ((size_t)b * SS + q0 + row) * K3 + hoff + col;
            const __nv_bfloat162 hi2 = __halves2bfloat162(h0, h1);
            *(__nv_bfloat162*)(x2 + base)        = hi2;
            *(__nv_bfloat162*)(x2 + base + 1024) = __halves2bfloat162(l0b, l1b);
            *(__nv_bfloat162*)(x2 + base + 2048) = hi2;
        }
    }
}

// ============================================================================
// launch
// ============================================================================
extern "C" void kernel_launch(void* const* d_in, const int* in_sizes, int n_in,
                              void* d_out, int out_size) {
    const float* q   = (const float*)d_in[0];
    const float* k   = (const float*)d_in[1];
    const float* v   = (const float*)d_in[2];
    const float* Wq  = (const float*)d_in[4];
    const float* bq  = (const float*)d_in[5];
    const float* Wk  = (const float*)d_in[6];
    const float* bk  = (const float*)d_in[7];
    const float* Wv  = (const float*)d_in[8];
    const float* bv  = (const float*)d_in[9];
    const float* W0  = (const float*)d_in[10];
    const float* b0  = (const float*)d_in[11];
    const float* rkt = (const float*)d_in[12];
    const float* rvt = (const float*)d_in[13];

    __nv_bfloat16 *Qh, *Ql, *Kh, *Kl, *Vh, *Vl;
    cudaGetSymbolAddress((void**)&Qh, g_Qh);
    cudaGetSymbolAddress((void**)&Ql, g_Ql);
    cudaGetSymbolAddress((void**)&Kh, g_Kh);
    cudaGetSymbolAddress((void**)&Kl, g_Kl);
    cudaGetSymbolAddress((void**)&Vh, g_Vh);
    cudaGetSymbolAddress((void**)&Vl, g_Vl);
    __nv_bfloat16 *q2, *k2, *v2, *x2, *wq2, *wk2, *wv2, *w02;
    cudaGetSymbolAddress((void**)&q2, g_q2);
    cudaGetSymbolAddress((void**)&k2, g_k2);
    cudaGetSymbolAddress((void**)&v2, g_v2);
    cudaGetSymbolAddress((void**)&x2, g_x2);
    cudaGetSymbolAddress((void**)&wq2, g_wq2);
    cudaGetSymbolAddress((void**)&wk2, g_wk2);
    cudaGetSymbolAddress((void**)&wv2, g_wv2);
    cudaGetSymbolAddress((void**)&w02, g_w02);

    const int M = BB * SS;          // 2048
    const int NACT = M * DMOD;      // 2M elements
    const int NW = DMOD * DMOD;     // 1M elements

    // batched splits: acts (q,k,v) and weights (Wq,Wk,Wv,W0)
    SplitPack ap;
    ap.in[0] = q;  ap.out[0] = q2;
    ap.in[1] = k;  ap.out[1] = k2;
    ap.in[2] = v;  ap.out[2] = v2;
    ap.in[3] = q;  ap.out[3] = q2;   // unused
    split_multi<<<dim3(NACT / 256, 3), 256>>>(ap, NACT, 1);
    SplitPack wp;
    wp.in[0] = Wq; wp.out[0] = wq2;
    wp.in[1] = Wk; wp.out[1] = wk2;
    wp.in[2] = Wv; wp.out[2] = wv2;
    wp.in[3] = W0; wp.out[3] = w02;
    split_multi<<<dim3(NW / 256, 4), 256>>>(wp, NW, 0);

    // fused q/k/v projections -> pre-split bf16 hi/lo planes
    GemmArgs pa;
    pa.A[0] = q2;  pa.A[1] = k2;  pa.A[2] = v2;
    pa.B[0] = wq2; pa.B[1] = wk2; pa.B[2] = wv2;
    pa.bias[0] = bq; pa.bias[1] = bk; pa.bias[2] = bv;
    pa.C[0] = pa.C[1] = pa.C[2] = nullptr;
    pa.Ch[0] = Qh; pa.Ch[1] = Kh; pa.Ch[2] = Vh;
    pa.Cl[0] = Ql; pa.Cl[1] = Kl; pa.Cl[2] = Vl;
    pa.mode = 1;
    gemm_mma<<<dim3(DMOD / 128, M / 128, 3), 256>>>(pa, DMOD);

    // tensor-core fused attention (pre-split operands, writes x2 directly)
    cudaFuncSetAttribute(attn_mma,
                         cudaFuncAttributeMaxDynamicSharedMemorySize, ATT_SMEM);
    attn_mma<<<dim3(SS / 128, HH, BB), 512, ATT_SMEM>>>(
        Qh, Ql, Kh, Kl, Vh, Vl, rkt, rvt, x2);

    // output projection (fp32 out)
    GemmArgs oa;
    oa.A[0] = x2;  oa.A[1] = x2;  oa.A[2] = x2;
    oa.B[0] = w02; oa.B[1] = w02; oa.B[2] = w02;
    oa.bias[0] = b0; oa.bias[1] = b0; oa.bias[2] = b0;
    oa.C[0] = (float*)d_out; oa.C[1] = (float*)d_out; oa.C[2] = (float*)d_out;
    oa.Ch[0] = oa.Ch[1] = oa.Ch[2] = nullptr;
    oa.Cl[0] = oa.Cl[1] = oa.Cl[2] = nullptr;
    oa.mode = 0;
    gemm_mma<<<dim3(DMOD / 128, M / 128, 1), 256>>>(oa, DMOD);
}